// round 2
// baseline (speedup 1.0000x reference)
#include <cuda_runtime.h>
#include <cstdint>

#define NY 64
#define NU 32
#define NH 512
#define NHRZ 2048
#define BB 128
#define LCH 64
#define PCH 32
#define KIN 544   // NH + NU

// ---------------- device scratch (static, no allocation) ----------------
__device__ float d_A[NH * NH];               // A (transposed recurrence weight), x' = x @ A
__device__ float d_Pow[6][NH * NH];          // A^2, A^4, A^8, A^16, A^32, A^64
__device__ float d_Cbuf[NH * LCH * NY];      // [512][4096], col block j = C_j = A^j Wy^T
__device__ float d_Gp[LCH * NU * NH];        // [2048][512], row block d = G'_d = Bm A^d
__device__ float d_Hd[(LCH - 1) * NU * NY];  // [63][32][64], Hd_d = Bm A^d Wy^T
__device__ float d_yb[LCH * NY];             // per-in-chunk-position output bias
__device__ float d_bL[NH];                   // bias aggregated over L steps
__device__ float d_Xc[(PCH + 1) * BB * NH];  // chunk-start states
__device__ float d_S[PCH * BB * NH];         // per-chunk aggregated inputs (+ bL)

// ---------------- tf32 helpers ----------------
__device__ __forceinline__ uint32_t f2tf(float x) {
    uint32_t r;
    asm("cvt.rna.tf32.f32 %0, %1;" : "=r"(r) : "f"(x));
    return r;
}

__device__ __forceinline__ void mma_tf32(float* c,
                                         uint32_t a0, uint32_t a1, uint32_t a2, uint32_t a3,
                                         uint32_t b0, uint32_t b1) {
    asm volatile(
        "mma.sync.aligned.m16n8k8.row.col.f32.tf32.tf32.f32 "
        "{%0,%1,%2,%3}, {%4,%5,%6,%7}, {%8,%9}, {%0,%1,%2,%3};"
        : "+f"(c[0]), "+f"(c[1]), "+f"(c[2]), "+f"(c[3])
        : "r"(a0), "r"(a1), "r"(a2), "r"(a3), "r"(b0), "r"(b1));
}

// ---------------- prep: transpose A, Bm, C0, x0 ----------------
__global__ void prep_kernel(const float* __restrict__ y0,
                            const float* __restrict__ y2x_w,
                            const float* __restrict__ y2x_b,
                            const float* __restrict__ xu2x_w,
                            const float* __restrict__ x2y_w) {
    int idx = blockIdx.x * blockDim.x + threadIdx.x;
    int stride = gridDim.x * blockDim.x;
    for (int t = idx; t < NH * NH; t += stride) {
        int p = t / NH, q = t % NH;
        d_A[p * NH + q] = xu2x_w[q * KIN + p];
    }
    for (int t = idx; t < NU * NH; t += stride) {
        int u = t / NH, h = t % NH;
        d_Gp[u * NH + h] = xu2x_w[h * KIN + NH + u];
    }
    for (int t = idx; t < NH * NY; t += stride) {
        int h = t / NY, n = t % NY;
        d_Cbuf[h * (LCH * NY) + n] = x2y_w[n * NH + h];
    }
    for (int t = idx; t < BB * NH; t += stride) {
        int b = t / NH, h = t % NH;
        float acc = y2x_b[h];
        #pragma unroll 8
        for (int n = 0; n < NY; n++) acc += y0[b * NY + n] * y2x_w[h * NY + n];
        d_Xc[b * NH + h] = acc;
    }
}

// ---------------- svec: bias chains yb_j, bL ----------------
__global__ void svec_kernel(const float* __restrict__ xu2x_w,
                            const float* __restrict__ xu2x_b,
                            const float* __restrict__ x2y_w,
                            const float* __restrict__ x2y_b) {
    __shared__ float s[NH];
    int t = threadIdx.x;
    s[t] = 0.0f;
    __syncthreads();
    for (int j = 0; j < LCH; j++) {
        if (t < NY) {
            float acc = x2y_b[t];
            for (int h = 0; h < NH; h++) acc += s[h] * x2y_w[t * NH + h];
            d_yb[j * NY + t] = acc;
        }
        float acc = xu2x_b[t];
        for (int p = 0; p < NH; p++) acc += s[p] * xu2x_w[t * KIN + p];
        __syncthreads();
        s[t] = acc;
        __syncthreads();
    }
    d_bL[t] = s[t];
}

// ---------------- generic small GEMM (fp32, precompute chain) ----------------
__global__ void gemm_small(const float* __restrict__ A, const float* __restrict__ B,
                           float* __restrict__ C, int K, int lda, int ldb, int ldc) {
    __shared__ float As[32][33];
    __shared__ float Bs[32][33];
    int tid = threadIdx.x;
    int tx = tid & 15, ty = tid >> 4;
    int row0 = blockIdx.y * 32, col0 = blockIdx.x * 32;
    float a00 = 0.f, a01 = 0.f, a10 = 0.f, a11 = 0.f;
    for (int k0 = 0; k0 < K; k0 += 32) {
        #pragma unroll
        for (int r = 0; r < 4; r++) {
            int e = tid + 256 * r;
            int ar = e >> 5, ac = e & 31;
            As[ar][ac] = A[(row0 + ar) * lda + k0 + ac];
            Bs[ar][ac] = B[(k0 + ar) * ldb + col0 + ac];
        }
        __syncthreads();
        #pragma unroll
        for (int k = 0; k < 32; k++) {
            float x0 = As[ty * 2 + 0][k], x1 = As[ty * 2 + 1][k];
            float w0 = Bs[k][tx * 2 + 0], w1 = Bs[k][tx * 2 + 1];
            a00 += x0 * w0; a01 += x0 * w1;
            a10 += x1 * w0; a11 += x1 * w1;
        }
        __syncthreads();
    }
    int r = row0 + ty * 2, c = col0 + tx * 2;
    C[r * ldc + c] = a00;       C[r * ldc + c + 1] = a01;
    C[(r + 1) * ldc + c] = a10; C[(r + 1) * ldc + c + 1] = a11;
}

// ---------------- S = Uchunk @ Grev + bL (tf32 MMA) ----------------
// grid: (NH/64, PCH); block 256 = 8 warps; tile M=128 (one chunk's batch) x N=64, K=2048
__global__ void s_mma_kernel(const float* __restrict__ U) {
    __shared__ uint32_t As[16][136];
    __shared__ uint32_t Bs[16][72];
    int tid = threadIdx.x;
    int warp = tid >> 5, lane = tid & 31;
    int gid = lane >> 2, tig = lane & 3;
    int p = blockIdx.y;
    int col0 = blockIdx.x * 64;
    float acc[8][4];
    #pragma unroll
    for (int i = 0; i < 8; i++)
        #pragma unroll
        for (int q = 0; q < 4; q++) acc[i][q] = 0.f;

    int mA = tid >> 1;
    int kqA = (tid & 1) * 8;
    int kbB = tid >> 4;
    int n4B = (tid & 15) * 4;
    long uBase = (long)p * (LCH * BB * NU) + (long)mA * NU;

    for (int k0 = 0; k0 < LCH * NU; k0 += 16) {
        #pragma unroll
        for (int h = 0; h < 2; h++) {
            int kk = k0 + kqA + h * 4;
            int i = kk >> 5, u = kk & 31;
            float4 v = *(const float4*)(U + uBase + (long)i * (BB * NU) + u);
            As[kqA + h * 4 + 0][mA] = f2tf(v.x);
            As[kqA + h * 4 + 1][mA] = f2tf(v.y);
            As[kqA + h * 4 + 2][mA] = f2tf(v.z);
            As[kqA + h * 4 + 3][mA] = f2tf(v.w);
        }
        {
            int kk = k0 + kbB;
            int i = kk >> 5, u = kk & 31;
            const float* brow = d_Gp + (size_t)((LCH - 1 - i) * NU + u) * NH + col0;
            float4 v = *(const float4*)(brow + n4B);
            uint4 w = {f2tf(v.x), f2tf(v.y), f2tf(v.z), f2tf(v.w)};
            *(uint4*)&Bs[kbB][n4B] = w;
        }
        __syncthreads();
        #pragma unroll
        for (int ks = 0; ks < 16; ks += 8) {
            uint32_t a0 = As[ks + tig][warp * 16 + gid];
            uint32_t a1 = As[ks + tig][warp * 16 + gid + 8];
            uint32_t a2 = As[ks + tig + 4][warp * 16 + gid];
            uint32_t a3 = As[ks + tig + 4][warp * 16 + gid + 8];
            #pragma unroll
            for (int nt = 0; nt < 8; nt++) {
                uint32_t b0 = Bs[ks + tig][nt * 8 + gid];
                uint32_t b1 = Bs[ks + tig + 4][nt * 8 + gid];
                mma_tf32(acc[nt], a0, a1, a2, a3, b0, b1);
            }
        }
        __syncthreads();
    }
    int r0 = p * BB + warp * 16 + gid;
    #pragma unroll
    for (int nt = 0; nt < 8; nt++) {
        int c = col0 + nt * 8 + 2 * tig;
        float bl0 = d_bL[c], bl1 = d_bL[c + 1];
        *(float2*)&d_S[(size_t)r0 * NH + c] = make_float2(acc[nt][0] + bl0, acc[nt][1] + bl1);
        *(float2*)&d_S[(size_t)(r0 + 8) * NH + c] = make_float2(acc[nt][2] + bl0, acc[nt][3] + bl1);
    }
}

// ---------------- sequential: Xc[p+1] = Xc[p] @ A^64 + S[p] (fp32) ----------------
__global__ void seq_kernel(int p) {
    __shared__ float As[32][33];
    __shared__ float Bs[32][33];
    int tid = threadIdx.x;
    int tx = tid & 15, ty = tid >> 4;
    int row0 = blockIdx.y * 32, col0 = blockIdx.x * 32;
    const float* Xp = d_Xc + (long)p * (BB * NH);
    const float* W  = d_Pow[5];
    float a00 = 0.f, a01 = 0.f, a10 = 0.f, a11 = 0.f;
    for (int k0 = 0; k0 < NH; k0 += 32) {
        #pragma unroll
        for (int r = 0; r < 4; r++) {
            int e = tid + 256 * r;
            int ar = e >> 5, ac = e & 31;
            As[ar][ac] = Xp[(row0 + ar) * NH + k0 + ac];
            Bs[ar][ac] = W[(k0 + ar) * NH + col0 + ac];
        }
        __syncthreads();
        #pragma unroll
        for (int k = 0; k < 32; k++) {
            float x0 = As[ty * 2 + 0][k], x1 = As[ty * 2 + 1][k];
            float w0 = Bs[k][tx * 2 + 0], w1 = Bs[k][tx * 2 + 1];
            a00 += x0 * w0; a01 += x0 * w1;
            a10 += x1 * w0; a11 += x1 * w1;
        }
        __syncthreads();
    }
    float* Xn = d_Xc + (long)(p + 1) * (BB * NH);
    const float* Sp = d_S + (long)p * (BB * NH);
    int r = row0 + ty * 2, c = col0 + tx * 2;
    Xn[r * NH + c]           = a00 + Sp[r * NH + c];
    Xn[r * NH + c + 1]       = a01 + Sp[r * NH + c + 1];
    Xn[(r + 1) * NH + c]     = a10 + Sp[(r + 1) * NH + c];
    Xn[(r + 1) * NH + c + 1] = a11 + Sp[(r + 1) * NH + c + 1];
}

// ---------------- output pass (tf32 MMA) ----------------
// block pj = p*64+j (and one extra for final state): Y[pj] = Xc[p] C_j + sum_i U[pL+i] Hd_{j-1-i} + yb_j
// tile M=128 x N=64, K = 512 + 32*j
__global__ void out_mma_kernel(const float* __restrict__ U, float* __restrict__ out) {
    __shared__ uint32_t As[16][136];
    __shared__ uint32_t Bs[16][72];
    int pj = blockIdx.x;
    int p = pj >> 6, j = pj & 63;
    int tid = threadIdx.x;
    int warp = tid >> 5, lane = tid & 31;
    int gid = lane >> 2, tig = lane & 3;
    int KT = 32 + 2 * j;

    float acc[8][4];
    #pragma unroll
    for (int i = 0; i < 8; i++)
        #pragma unroll
        for (int q = 0; q < 4; q++) acc[i][q] = 0.f;

    int mA = tid >> 1;
    int kqA = (tid & 1) * 8;
    int kbB = tid >> 4;
    int n4B = (tid & 15) * 4;
    const float* xcRow = d_Xc + (size_t)p * (BB * NH) + (size_t)mA * NH;
    long uBase = (long)p * (LCH * BB * NU) + (long)mA * NU;

    for (int kt = 0; kt < KT; kt++) {
        int k0 = kt * 16;
        #pragma unroll
        for (int h = 0; h < 2; h++) {
            int kk = k0 + kqA + h * 4;
            float4 v;
            if (kk < NH) {
                v = *(const float4*)(xcRow + kk);
            } else {
                int kc = kk - NH;
                int i = kc >> 5, u = kc & 31;
                v = *(const float4*)(U + uBase + (long)i * (BB * NU) + u);
            }
            As[kqA + h * 4 + 0][mA] = f2tf(v.x);
            As[kqA + h * 4 + 1][mA] = f2tf(v.y);
            As[kqA + h * 4 + 2][mA] = f2tf(v.z);
            As[kqA + h * 4 + 3][mA] = f2tf(v.w);
        }
        {
            int kk = k0 + kbB;
            const float* brow;
            if (kk < NH) {
                brow = d_Cbuf + (size_t)kk * (LCH * NY) + j * NY;
            } else {
                int kc = kk - NH;
                int i = kc >> 5, u = kc & 31;
                brow = d_Hd + (size_t)((j - 1 - i) * NU + u) * NY;
            }
            float4 v = *(const float4*)(brow + n4B);
            uint4 w = {f2tf(v.x), f2tf(v.y), f2tf(v.z), f2tf(v.w)};
            *(uint4*)&Bs[kbB][n4B] = w;
        }
        __syncthreads();
        #pragma unroll
        for (int ks = 0; ks < 16; ks += 8) {
            uint32_t a0 = As[ks + tig][warp * 16 + gid];
            uint32_t a1 = As[ks + tig][warp * 16 + gid + 8];
            uint32_t a2 = As[ks + tig + 4][warp * 16 + gid];
            uint32_t a3 = As[ks + tig + 4][warp * 16 + gid + 8];
            #pragma unroll
            for (int nt = 0; nt < 8; nt++) {
                uint32_t b0 = Bs[ks + tig][nt * 8 + gid];
                uint32_t b1 = Bs[ks + tig + 4][nt * 8 + gid];
                mma_tf32(acc[nt], a0, a1, a2, a3, b0, b1);
            }
        }
        __syncthreads();
    }
    float* orow = out + (size_t)pj * (BB * NY);
    int r0 = warp * 16 + gid;
    #pragma unroll
    for (int nt = 0; nt < 8; nt++) {
        int c = nt * 8 + 2 * tig;
        float yb0 = d_yb[j * NY + c], yb1 = d_yb[j * NY + c + 1];
        *(float2*)&orow[(size_t)r0 * NY + c] = make_float2(acc[nt][0] + yb0, acc[nt][1] + yb1);
        *(float2*)&orow[(size_t)(r0 + 8) * NY + c] = make_float2(acc[nt][2] + yb0, acc[nt][3] + yb1);
    }
}

// ---------------- host ----------------
extern "C" void kernel_launch(void* const* d_in, const int* in_sizes, int n_in,
                              void* d_out, int out_size) {
    const float* y0     = (const float*)d_in[0];
    const float* U      = (const float*)d_in[1];
    const float* y2x_w  = (const float*)d_in[2];
    const float* y2x_b  = (const float*)d_in[3];
    const float* xu2x_w = (const float*)d_in[4];
    const float* xu2x_b = (const float*)d_in[5];
    const float* x2y_w  = (const float*)d_in[6];
    const float* x2y_b  = (const float*)d_in[7];
    float* out = (float*)d_out;

    float *pA, *pP, *pCbuf, *pGp, *pHd;
    cudaGetSymbolAddress((void**)&pA, d_A);
    cudaGetSymbolAddress((void**)&pP, d_Pow);
    cudaGetSymbolAddress((void**)&pCbuf, d_Cbuf);
    cudaGetSymbolAddress((void**)&pGp, d_Gp);
    cudaGetSymbolAddress((void**)&pHd, d_Hd);
    const int SZ = NH * NH;

    prep_kernel<<<128, 256>>>(y0, y2x_w, y2x_b, xu2x_w, x2y_w);
    svec_kernel<<<1, NH>>>(xu2x_w, xu2x_b, x2y_w, x2y_b);

    // A^2 .. A^64 by squaring
    gemm_small<<<dim3(16, 16), 256>>>(pA, pA, pP + 0 * SZ, NH, NH, NH, NH);
    for (int k = 1; k < 6; k++)
        gemm_small<<<dim3(16, 16), 256>>>(pP + (k - 1) * SZ, pP + (k - 1) * SZ, pP + k * SZ,
                                          NH, NH, NH, NH);

    // C_j doubling: C[j+2^k] = A^{2^k} @ C[j]
    for (int k = 0; k < 6; k++) {
        const float* mult = (k == 0) ? pA : (pP + (k - 1) * SZ);
        int w = NY << k;
        gemm_small<<<dim3(w / 32, 16), 256>>>(mult, pCbuf, pCbuf + w, NH, NH, LCH * NY, LCH * NY);
    }
    // G'_d doubling: G'[d+2^k] = G'[d] @ A^{2^k}
    for (int k = 0; k < 6; k++) {
        const float* mult = (k == 0) ? pA : (pP + (k - 1) * SZ);
        int rows = NU << k;
        gemm_small<<<dim3(16, rows / 32), 256>>>(pGp, mult, pGp + rows * NH, NH, NH, NH, NH);
    }
    // Hd_d = G'_d @ C_0  (stacked M = 63*32 = 2016)
    gemm_small<<<dim3(2, 63), 256>>>(pGp, pCbuf, pHd, NH, NH, LCH * NY, NY);

    // S = Uchunk @ Grev + bL  (tf32)
    s_mma_kernel<<<dim3(NH / 64, PCH), 256>>>(U);

    // 32 sequential chunk steps (fp32)
    for (int p = 0; p < PCH; p++)
        seq_kernel<<<dim3(NH / 32, BB / 32), 256>>>(p);

    // output pass: 2049 (p,j) tiles (tf32)
    out_mma_kernel<<<PCH * LCH + 1, 256>>>(U, out);

    (void)in_sizes; (void)n_in; (void)out_size;
}

// round 3
// speedup vs baseline: 1.6323x; 1.6323x over previous
#include <cuda_runtime.h>
#include <cstdint>

#define NY 64
#define NU 32
#define NH 512
#define NHRZ 2048
#define BB 128
#define LCH 32
#define PCH 64
#define KIN 544   // NH + NU

typedef unsigned long long ull;

// ---------------- device scratch ----------------
__device__ float d_A[NH * NH];
__device__ float d_Pow[6][NH * NH];          // A^2,4,8,16,32,64
__device__ float d_Cbuf[NH * LCH * NY];      // [512][2048] col block j = A^j Wy^T
__device__ float d_Gp[LCH * NU * NH];        // [1024][512] row block d = Bm A^d
__device__ float d_Hd[(LCH - 1) * NU * NY];  // [31][32][64]
__device__ float d_yb[LCH * NY];
__device__ float d_bL[NH];
__device__ float d_Xc[(PCH + 1) * BB * NH];  // chunk-start states (every 32 steps)
__device__ float d_S32[PCH * BB * NH];
__device__ float d_S64[(PCH / 2) * BB * NH];

// ---------------- f32x2 helpers ----------------
__device__ __forceinline__ ull pk2(float x) {
    ull r;
    asm("mov.b64 %0, {%1, %1};" : "=l"(r) : "f"(x));
    return r;
}
__device__ __forceinline__ void fma2(ull& d, ull a, ull b) {
    asm("fma.rn.f32x2 %0, %1, %2, %0;" : "+l"(d) : "l"(a), "l"(b));
}
__device__ __forceinline__ float2 up2(ull v) {
    float2 f;
    asm("mov.b64 {%0, %1}, %2;" : "=f"(f.x), "=f"(f.y) : "l"(v));
    return f;
}

// ---------------- shared compute core: 128x64 tile, 16-k slab ----------------
__device__ __forceinline__ void core16(const float (*As)[132], const float (*Bs)[68],
                                       int ty, int tx, ull acc[4][4]) {
    #pragma unroll
    for (int k = 0; k < 16; k++) {
        float4 av = *(const float4*)&As[k][ty * 4];
        ulonglong2 b0 = *(const ulonglong2*)&Bs[k][tx * 4];
        ulonglong2 b1 = *(const ulonglong2*)&Bs[k][tx * 4 + 32];
        ull pa;
        pa = pk2(av.x);
        fma2(acc[0][0], pa, b0.x); fma2(acc[0][1], pa, b0.y);
        fma2(acc[0][2], pa, b1.x); fma2(acc[0][3], pa, b1.y);
        pa = pk2(av.y);
        fma2(acc[1][0], pa, b0.x); fma2(acc[1][1], pa, b0.y);
        fma2(acc[1][2], pa, b1.x); fma2(acc[1][3], pa, b1.y);
        pa = pk2(av.z);
        fma2(acc[2][0], pa, b0.x); fma2(acc[2][1], pa, b0.y);
        fma2(acc[2][2], pa, b1.x); fma2(acc[2][3], pa, b1.y);
        pa = pk2(av.w);
        fma2(acc[3][0], pa, b0.x); fma2(acc[3][1], pa, b0.y);
        fma2(acc[3][2], pa, b1.x); fma2(acc[3][3], pa, b1.y);
    }
}

__device__ __forceinline__ void stsA(float (*As)[132], int kq, int m, float4 a, float4 b) {
    As[kq + 0][m] = a.x; As[kq + 1][m] = a.y; As[kq + 2][m] = a.z; As[kq + 3][m] = a.w;
    As[kq + 4][m] = b.x; As[kq + 5][m] = b.y; As[kq + 6][m] = b.z; As[kq + 7][m] = b.w;
}

// ---------------- prep ----------------
__global__ void prep_kernel(const float* __restrict__ y0,
                            const float* __restrict__ y2x_w,
                            const float* __restrict__ y2x_b,
                            const float* __restrict__ xu2x_w,
                            const float* __restrict__ x2y_w) {
    int idx = blockIdx.x * blockDim.x + threadIdx.x;
    int stride = gridDim.x * blockDim.x;
    for (int t = idx; t < NH * NH; t += stride) {
        int p = t / NH, q = t % NH;
        d_A[p * NH + q] = xu2x_w[q * KIN + p];
    }
    for (int t = idx; t < NU * NH; t += stride) {
        int u = t / NH, h = t % NH;
        d_Gp[u * NH + h] = xu2x_w[h * KIN + NH + u];
    }
    for (int t = idx; t < NH * NY; t += stride) {
        int h = t / NY, n = t % NY;
        d_Cbuf[h * (LCH * NY) + n] = x2y_w[n * NH + h];
    }
    for (int t = idx; t < BB * NH; t += stride) {
        int b = t / NH, h = t % NH;
        float acc = y2x_b[h];
        #pragma unroll 8
        for (int n = 0; n < NY; n++) acc += y0[b * NY + n] * y2x_w[h * NY + n];
        d_Xc[b * NH + h] = acc;
    }
}

// ---------------- svec ----------------
__global__ void svec_kernel(const float* __restrict__ xu2x_w,
                            const float* __restrict__ xu2x_b,
                            const float* __restrict__ x2y_w,
                            const float* __restrict__ x2y_b) {
    __shared__ float s[NH];
    int t = threadIdx.x;
    s[t] = 0.0f;
    __syncthreads();
    for (int j = 0; j < LCH; j++) {
        if (t < NY) {
            float acc = x2y_b[t];
            for (int h = 0; h < NH; h++) acc += s[h] * x2y_w[t * NH + h];
            d_yb[j * NY + t] = acc;
        }
        float acc = xu2x_b[t];
        for (int p = 0; p < NH; p++) acc += s[p] * xu2x_w[t * KIN + p];
        __syncthreads();
        s[t] = acc;
        __syncthreads();
    }
    d_bL[t] = s[t];
}

// ---------------- fat generic GEMM: C = A@B (+Add), 128x64 tile ----------------
__global__ void __launch_bounds__(256) gemm_f(
    const float* __restrict__ A, long aBatch, int lda,
    const float* __restrict__ B, int ldb,
    const float* __restrict__ Add, long addBatch,
    float* __restrict__ C, long cBatch, int ldc, int K)
{
    __shared__ float As[2][16][132];
    __shared__ float Bs[2][16][68];
    int t = threadIdx.x;
    int col0 = blockIdx.x * 64;
    long q = blockIdx.y;

    int mA = t >> 1, kqA = (t & 1) * 8;
    int kbB = t >> 4, n4B = (t & 15) * 4;
    const float* Arow = A + q * aBatch + (long)mA * lda;

    int tx = t & 7, ty = t >> 3;
    ull acc[4][4];
    #pragma unroll
    for (int i = 0; i < 4; i++)
        #pragma unroll
        for (int jj = 0; jj < 4; jj++) acc[i][jj] = 0ull;

    float4 ra0, ra1, rb;
    ra0 = *(const float4*)(Arow + kqA);
    ra1 = *(const float4*)(Arow + kqA + 4);
    rb  = *(const float4*)(B + (long)kbB * ldb + col0 + n4B);
    stsA(As[0], kqA, mA, ra0, ra1);
    *(float4*)&Bs[0][kbB][n4B] = rb;
    __syncthreads();

    int KT = K >> 4;
    for (int kt = 0; kt < KT; kt++) {
        int cur = kt & 1;
        bool more = (kt + 1 < KT);
        if (more) {
            int k0 = (kt + 1) * 16;
            ra0 = *(const float4*)(Arow + k0 + kqA);
            ra1 = *(const float4*)(Arow + k0 + kqA + 4);
            rb  = *(const float4*)(B + (long)(k0 + kbB) * ldb + col0 + n4B);
        }
        core16(As[cur], Bs[cur], ty, tx, acc);
        if (more) {
            stsA(As[cur ^ 1], kqA, mA, ra0, ra1);
            *(float4*)&Bs[cur ^ 1][kbB][n4B] = rb;
        }
        __syncthreads();
    }

    #pragma unroll
    for (int e = 0; e < 4; e++) {
        int r = ty * 4 + e;
        float2 x0 = up2(acc[e][0]), x1 = up2(acc[e][1]);
        float2 x2 = up2(acc[e][2]), x3 = up2(acc[e][3]);
        float4 v0 = make_float4(x0.x, x0.y, x1.x, x1.y);
        float4 v1 = make_float4(x2.x, x2.y, x3.x, x3.y);
        long off = (long)r * ldc + col0 + tx * 4;
        if (Add != nullptr) {
            const float* ap = Add + q * addBatch + off;
            float4 a0 = *(const float4*)ap;
            float4 a1 = *(const float4*)(ap + 32);
            v0.x += a0.x; v0.y += a0.y; v0.z += a0.z; v0.w += a0.w;
            v1.x += a1.x; v1.y += a1.y; v1.z += a1.z; v1.w += a1.w;
        }
        float* cp = C + q * cBatch + off;
        *(float4*)cp = v0;
        *(float4*)(cp + 32) = v1;
    }
}

// ---------------- S32 = Uchunk @ Grev + bL ----------------
__global__ void __launch_bounds__(256) s32_kernel(const float* __restrict__ U) {
    __shared__ float As[2][16][132];
    __shared__ float Bs[2][16][68];
    int t = threadIdx.x;
    int col0 = blockIdx.x * 64;
    int q = blockIdx.y;

    int mA = t >> 1, kqA = (t & 1) * 8;
    int kbB = t >> 4, n4B = (t & 15) * 4;
    long uBase = (long)q * (LCH * BB * NU) + (long)mA * NU;

    int tx = t & 7, ty = t >> 3;
    ull acc[4][4];
    #pragma unroll
    for (int i = 0; i < 4; i++)
        #pragma unroll
        for (int jj = 0; jj < 4; jj++) acc[i][jj] = 0ull;

    float4 ra0, ra1, rb;
    {
        int kk = kqA;
        ra0 = *(const float4*)(U + uBase + (long)(kk >> 5) * (BB * NU) + (kk & 31));
        kk += 4;
        ra1 = *(const float4*)(U + uBase + (long)(kk >> 5) * (BB * NU) + (kk & 31));
        int kb = kbB;
        rb = *(const float4*)(d_Gp + (long)((31 - (kb >> 5)) * NU + (kb & 31)) * NH + col0 + n4B);
    }
    stsA(As[0], kqA, mA, ra0, ra1);
    *(float4*)&Bs[0][kbB][n4B] = rb;
    __syncthreads();

    const int KT = (LCH * NU) >> 4;  // 64
    for (int kt = 0; kt < KT; kt++) {
        int cur = kt & 1;
        bool more = (kt + 1 < KT);
        if (more) {
            int k0 = (kt + 1) * 16;
            int kk = k0 + kqA;
            ra0 = *(const float4*)(U + uBase + (long)(kk >> 5) * (BB * NU) + (kk & 31));
            kk += 4;
            ra1 = *(const float4*)(U + uBase + (long)(kk >> 5) * (BB * NU) + (kk & 31));
            int kb = k0 + kbB;
            rb = *(const float4*)(d_Gp + (long)((31 - (kb >> 5)) * NU + (kb & 31)) * NH + col0 + n4B);
        }
        core16(As[cur], Bs[cur], ty, tx, acc);
        if (more) {
            stsA(As[cur ^ 1], kqA, mA, ra0, ra1);
            *(float4*)&Bs[cur ^ 1][kbB][n4B] = rb;
        }
        __syncthreads();
    }

    float4 bl0 = *(const float4*)&d_bL[col0 + tx * 4];
    float4 bl1 = *(const float4*)&d_bL[col0 + tx * 4 + 32];
    #pragma unroll
    for (int e = 0; e < 4; e++) {
        int r = ty * 4 + e;
        float2 x0 = up2(acc[e][0]), x1 = up2(acc[e][1]);
        float2 x2 = up2(acc[e][2]), x3 = up2(acc[e][3]);
        float4 v0 = make_float4(x0.x + bl0.x, x0.y + bl0.y, x1.x + bl0.z, x1.y + bl0.w);
        float4 v1 = make_float4(x2.x + bl1.x, x2.y + bl1.y, x3.x + bl1.z, x3.y + bl1.w);
        float* cp = d_S32 + (long)q * (BB * NH) + (long)r * NH + col0 + tx * 4;
        *(float4*)cp = v0;
        *(float4*)(cp + 32) = v1;
    }
}

// ---------------- sequential step: D = X @ W + Add, 32x64 tiles ----------------
__global__ void __launch_bounds__(256) seq_step(const float* __restrict__ X,
                                                const float* __restrict__ W,
                                                const float* __restrict__ Addp,
                                                float* __restrict__ D) {
    __shared__ float As[2][16][33];
    __shared__ float Bs[2][16][68];
    int t = threadIdx.x;
    int col0 = blockIdx.x * 64;
    int row0 = blockIdx.y * 32;
    int mA = t >> 3, kpA = (t & 7) * 2;
    int kbB = t >> 4, n4B = (t & 15) * 4;
    int tx = t & 15, ty = t >> 4;
    ull acc[2][2] = {{0ull, 0ull}, {0ull, 0ull}};
    const float* Arow = X + (long)(row0 + mA) * NH;

    float2 ra; float4 rb;
    ra = *(const float2*)(Arow + kpA);
    rb = *(const float4*)(W + (long)kbB * NH + col0 + n4B);
    As[0][kpA][mA] = ra.x; As[0][kpA + 1][mA] = ra.y;
    *(float4*)&Bs[0][kbB][n4B] = rb;
    __syncthreads();

    const int KT = NH >> 4;  // 32
    for (int kt = 0; kt < KT; kt++) {
        int cur = kt & 1;
        bool more = (kt + 1 < KT);
        if (more) {
            int k0 = (kt + 1) * 16;
            ra = *(const float2*)(Arow + k0 + kpA);
            rb = *(const float4*)(W + (long)(k0 + kbB) * NH + col0 + n4B);
        }
        #pragma unroll
        for (int k = 0; k < 16; k++) {
            float a0 = As[cur][k][ty * 2], a1 = As[cur][k][ty * 2 + 1];
            ull b0 = *(const ull*)&Bs[cur][k][tx * 2];
            ull b1 = *(const ull*)&Bs[cur][k][tx * 2 + 32];
            ull p0 = pk2(a0), p1 = pk2(a1);
            fma2(acc[0][0], p0, b0); fma2(acc[0][1], p0, b1);
            fma2(acc[1][0], p1, b0); fma2(acc[1][1], p1, b1);
        }
        if (more) {
            As[cur ^ 1][kpA][mA] = ra.x; As[cur ^ 1][kpA + 1][mA] = ra.y;
            *(float4*)&Bs[cur ^ 1][kbB][n4B] = rb;
        }
        __syncthreads();
    }

    #pragma unroll
    for (int e = 0; e < 2; e++) {
        int r = row0 + ty * 2 + e;
        float2 v0 = up2(acc[e][0]);
        float2 v1 = up2(acc[e][1]);
        const float* ap = Addp + (long)r * NH + col0 + tx * 2;
        float2 a0 = *(const float2*)ap;
        float2 a1 = *(const float2*)(ap + 32);
        v0.x += a0.x; v0.y += a0.y;
        v1.x += a1.x; v1.y += a1.y;
        float* dp = D + (long)r * NH + col0 + tx * 2;
        *(float2*)dp = v0;
        *(float2*)(dp + 32) = v1;
    }
}

// ---------------- output pass: Y[pj] = Xc[p]C_j + causal U*Hd + yb_j ----------------
__global__ void __launch_bounds__(256) out_kernel(const float* __restrict__ U,
                                                  float* __restrict__ out) {
    __shared__ float As[2][16][132];
    __shared__ float Bs[2][16][68];
    int pj = blockIdx.x;
    int p = pj >> 5, j = pj & 31;
    int t = threadIdx.x;
    int KT = 32 + 2 * j;

    int mA = t >> 1, kqA = (t & 1) * 8;
    int kbB = t >> 4, n4B = (t & 15) * 4;
    const float* xcRow = d_Xc + (long)p * (BB * NH) + (long)mA * NH;
    long uBase = (long)p * (LCH * BB * NU) + (long)mA * NU;

    int tx = t & 7, ty = t >> 3;
    ull acc[4][4];
    #pragma unroll
    for (int i = 0; i < 4; i++)
        #pragma unroll
        for (int jj = 0; jj < 4; jj++) acc[i][jj] = 0ull;

    float4 ra0, ra1, rb;
    // prologue tile 0 is always in the Xc/Cbuf region
    ra0 = *(const float4*)(xcRow + kqA);
    ra1 = *(const float4*)(xcRow + kqA + 4);
    rb  = *(const float4*)(d_Cbuf + (long)kbB * (LCH * NY) + j * NY + n4B);
    stsA(As[0], kqA, mA, ra0, ra1);
    *(float4*)&Bs[0][kbB][n4B] = rb;
    __syncthreads();

    for (int kt = 0; kt < KT; kt++) {
        int cur = kt & 1;
        bool more = (kt + 1 < KT);
        if (more) {
            int k0 = (kt + 1) * 16;
            int kk = k0 + kqA;
            if (kk < NH) {
                ra0 = *(const float4*)(xcRow + kk);
                ra1 = *(const float4*)(xcRow + kk + 4);
            } else {
                int kc = kk - NH;
                ra0 = *(const float4*)(U + uBase + (long)(kc >> 5) * (BB * NU) + (kc & 31));
                kc += 4;
                ra1 = *(const float4*)(U + uBase + (long)(kc >> 5) * (BB * NU) + (kc & 31));
            }
            int kb = k0 + kbB;
            if (kb < NH) {
                rb = *(const float4*)(d_Cbuf + (long)kb * (LCH * NY) + j * NY + n4B);
            } else {
                int kc = kb - NH;
                rb = *(const float4*)(d_Hd + (long)((j - 1 - (kc >> 5)) * NU + (kc & 31)) * NY + n4B);
            }
        }
        core16(As[cur], Bs[cur], ty, tx, acc);
        if (more) {
            stsA(As[cur ^ 1], kqA, mA, ra0, ra1);
            *(float4*)&Bs[cur ^ 1][kbB][n4B] = rb;
        }
        __syncthreads();
    }

    float4 yb0 = *(const float4*)(d_yb + j * NY + tx * 4);
    float4 yb1 = *(const float4*)(d_yb + j * NY + tx * 4 + 32);
    float* obase = out + (long)pj * (BB * NY);
    #pragma unroll
    for (int e = 0; e < 4; e++) {
        int r = ty * 4 + e;
        float2 x0 = up2(acc[e][0]), x1 = up2(acc[e][1]);
        float2 x2 = up2(acc[e][2]), x3 = up2(acc[e][3]);
        float4 v0 = make_float4(x0.x + yb0.x, x0.y + yb0.y, x1.x + yb0.z, x1.y + yb0.w);
        float4 v1 = make_float4(x2.x + yb1.x, x2.y + yb1.y, x3.x + yb1.z, x3.y + yb1.w);
        float* op = obase + (long)r * NY + tx * 4;
        *(float4*)op = v0;
        *(float4*)(op + 32) = v1;
    }
}

// ---------------- small GEMM (Gp/Hd chains) ----------------
__global__ void gemm_small(const float* __restrict__ A, const float* __restrict__ B,
                           float* __restrict__ C, int K, int lda, int ldb, int ldc) {
    __shared__ float As[32][33];
    __shared__ float Bs[32][33];
    int tid = threadIdx.x;
    int tx = tid & 15, ty = tid >> 4;
    int row0 = blockIdx.y * 32, col0 = blockIdx.x * 32;
    float a00 = 0.f, a01 = 0.f, a10 = 0.f, a11 = 0.f;
    for (int k0 = 0; k0 < K; k0 += 32) {
        #pragma unroll
        for (int r = 0; r < 4; r++) {
            int e = tid + 256 * r;
            int ar = e >> 5, ac = e & 31;
            As[ar][ac] = A[(row0 + ar) * lda + k0 + ac];
            Bs[ar][ac] = B[(k0 + ar) * ldb + col0 + ac];
        }
        __syncthreads();
        #pragma unroll
        for (int k = 0; k < 32; k++) {
            float x0 = As[ty * 2 + 0][k], x1 = As[ty * 2 + 1][k];
            float w0 = Bs[k][tx * 2 + 0], w1 = Bs[k][tx * 2 + 1];
            a00 += x0 * w0; a01 += x0 * w1;
            a10 += x1 * w0; a11 += x1 * w1;
        }
        __syncthreads();
    }
    int r = row0 + ty * 2, c = col0 + tx * 2;
    C[r * ldc + c] = a00;       C[r * ldc + c + 1] = a01;
    C[(r + 1) * ldc + c] = a10; C[(r + 1) * ldc + c + 1] = a11;
}

// ---------------- host ----------------
extern "C" void kernel_launch(void* const* d_in, const int* in_sizes, int n_in,
                              void* d_out, int out_size) {
    const float* y0     = (const float*)d_in[0];
    const float* U      = (const float*)d_in[1];
    const float* y2x_w  = (const float*)d_in[2];
    const float* y2x_b  = (const float*)d_in[3];
    const float* xu2x_w = (const float*)d_in[4];
    const float* xu2x_b = (const float*)d_in[5];
    const float* x2y_w  = (const float*)d_in[6];
    const float* x2y_b  = (const float*)d_in[7];
    float* out = (float*)d_out;

    float *pA, *pP, *pCbuf, *pGp, *pHd, *pXc, *pS32, *pS64;
    cudaGetSymbolAddress((void**)&pA, d_A);
    cudaGetSymbolAddress((void**)&pP, d_Pow);
    cudaGetSymbolAddress((void**)&pCbuf, d_Cbuf);
    cudaGetSymbolAddress((void**)&pGp, d_Gp);
    cudaGetSymbolAddress((void**)&pHd, d_Hd);
    cudaGetSymbolAddress((void**)&pXc, d_Xc);
    cudaGetSymbolAddress((void**)&pS32, d_S32);
    cudaGetSymbolAddress((void**)&pS64, d_S64);
    const long SZ = NH * NH;
    const long CH = (long)BB * NH;  // 65536 floats per chunk-state

    prep_kernel<<<128, 256>>>(y0, y2x_w, y2x_b, xu2x_w, x2y_w);
    svec_kernel<<<1, NH>>>(xu2x_w, xu2x_b, x2y_w, x2y_b);

    // A^2 .. A^64 by squaring (fat gemm: M=512 -> grid (8,4))
    gemm_f<<<dim3(8, 4), 256>>>(pA, 128L * NH, NH, pA, NH, nullptr, 0, pP, 128L * NH, NH, NH);
    for (int k = 1; k < 6; k++)
        gemm_f<<<dim3(8, 4), 256>>>(pP + (k - 1) * SZ, 128L * NH, NH,
                                    pP + (k - 1) * SZ, NH, nullptr, 0,
                                    pP + k * SZ, 128L * NH, NH, NH);

    // C_j doubling: C[j+2^k] = A^{2^k} @ C[j],  j < 2^k
    for (int k = 0; k < 5; k++) {
        const float* mult = (k == 0) ? pA : (pP + (k - 1) * SZ);
        int w = NY << k;  // 64,128,256,512,1024 columns present
        gemm_f<<<dim3(w / 64, 4), 256>>>(mult, 128L * NH, NH,
                                         pCbuf, LCH * NY, nullptr, 0,
                                         pCbuf + w, 128L * (LCH * NY), LCH * NY, NH);
    }
    // G'_d doubling: G'[d+2^k] = G'[d] @ A^{2^k}
    for (int k = 0; k < 5; k++) {
        const float* mult = (k == 0) ? pA : (pP + (k - 1) * SZ);
        int rows = NU << k;
        gemm_small<<<dim3(16, rows / 32), 256>>>(pGp, mult, pGp + rows * NH, NH, NH, NH, NH);
    }
    // Hd_d = G'_d @ C_0 (stacked M = 31*32 = 992)
    gemm_small<<<dim3(2, 31), 256>>>(pGp, pCbuf, pHd, NH, NH, LCH * NY, NY);

    // S32[q] = Uchunk_q @ Grev + bL
    s32_kernel<<<dim3(NH / 64, PCH), 256>>>(U);

    // S64[p] = S32[2p] @ A^32 + S32[2p+1]
    gemm_f<<<dim3(8, PCH / 2), 256>>>(pS32, 2L * CH, NH, pP + 4 * SZ, NH,
                                      pS32 + CH, 2L * CH, pS64, CH, NH, NH);

    // 32 sequential steps: Xc[2p+2] = Xc[2p] @ A^64 + S64[p]
    for (int p = 0; p < PCH / 2; p++)
        seq_step<<<dim3(8, 4), 256>>>(pXc + 2L * p * CH, pP + 5 * SZ,
                                      pS64 + (long)p * CH, pXc + (2L * p + 2) * CH);

    // fill odd states: Xc[2p+1] = Xc[2p] @ A^32 + S32[2p]
    gemm_f<<<dim3(8, PCH / 2), 256>>>(pXc, 2L * CH, NH, pP + 4 * SZ, NH,
                                      pS32, 2L * CH, pXc + CH, 2L * CH, NH, NH);

    // output pass: 2049 (p,j) tiles
    out_kernel<<<PCH * LCH + 1, 256>>>(U, out);

    (void)in_sizes; (void)n_in; (void)out_size;
}

// round 4
// speedup vs baseline: 3.3762x; 2.0683x over previous
#include <cuda_runtime.h>
#include <cstdint>

#define NY 64
#define NU 32
#define NH 512
#define NHRZ 2048
#define BB 128
#define LCH 32
#define PCH 64
#define KIN 544   // NH + NU
#define CH (BB * NH)

typedef unsigned long long ull;

// ---------------- device scratch ----------------
__device__ float d_A[NH * NH];
__device__ float d_Pow[7][NH * NH];          // A^2,4,8,16,32,64,128
__device__ float d_Cbuf[NH * LCH * NY];      // [512][2048] col block j = A^j Wy^T
__device__ float d_Gp[LCH * NU * NH];        // [1024][512] row block d = Bm A^d
__device__ float d_Hd[LCH * NU * NY];        // [32][32][64] (d=31 unused)
__device__ float d_yb[LCH * NY];
__device__ float d_bL[NH];
__device__ float d_Xc[(PCH + 1) * CH];       // states every 32 steps
__device__ float d_S32[PCH * CH];
__device__ float d_S64[(PCH / 2) * CH];
__device__ float d_S128[(PCH / 4) * CH];
__device__ unsigned d_bar;

// ---------------- f32x2 helpers ----------------
__device__ __forceinline__ ull pk2(float x) {
    ull r;
    asm("mov.b64 %0, {%1, %1};" : "=l"(r) : "f"(x));
    return r;
}
__device__ __forceinline__ void fma2(ull& d, ull a, ull b) {
    asm("fma.rn.f32x2 %0, %1, %2, %0;" : "+l"(d) : "l"(a), "l"(b));
}
__device__ __forceinline__ float2 up2(ull v) {
    float2 f;
    asm("mov.b64 {%0, %1}, %2;" : "=f"(f.x), "=f"(f.y) : "l"(v));
    return f;
}

// ---------------- 8x8 core: 128 threads, tile 128x64, 16-k slab ----------------
// tx8 = (t&7)*8 -> 8 cols, ty8 = (t>>3)*8 -> 8 rows
__device__ __forceinline__ void core8x8(const float (*As)[132], const float (*Bs)[68],
                                        int ty8, int tx8, ull acc[8][4]) {
    #pragma unroll
    for (int k = 0; k < 16; k++) {
        float4 a0 = *(const float4*)&As[k][ty8];
        float4 a1 = *(const float4*)&As[k][ty8 + 4];
        ulonglong2 b0 = *(const ulonglong2*)&Bs[k][tx8];
        ulonglong2 b1 = *(const ulonglong2*)&Bs[k][tx8 + 4];
        float ar0[4] = {a0.x, a0.y, a0.z, a0.w};
        float ar1[4] = {a1.x, a1.y, a1.z, a1.w};
        #pragma unroll
        for (int r = 0; r < 4; r++) {
            ull pa = pk2(ar0[r]);
            fma2(acc[r][0], pa, b0.x); fma2(acc[r][1], pa, b0.y);
            fma2(acc[r][2], pa, b1.x); fma2(acc[r][3], pa, b1.y);
        }
        #pragma unroll
        for (int r = 0; r < 4; r++) {
            ull pa = pk2(ar1[r]);
            fma2(acc[4 + r][0], pa, b0.x); fma2(acc[4 + r][1], pa, b0.y);
            fma2(acc[4 + r][2], pa, b1.x); fma2(acc[4 + r][3], pa, b1.y);
        }
    }
}

__device__ __forceinline__ void stsA16(float (*As)[132], int t, const float4* ra) {
    #pragma unroll
    for (int h = 0; h < 4; h++) {
        As[h * 4 + 0][t] = ra[h].x;
        As[h * 4 + 1][t] = ra[h].y;
        As[h * 4 + 2][t] = ra[h].z;
        As[h * 4 + 3][t] = ra[h].w;
    }
}

// ---------------- transpose A (smem tiled) ----------------
__global__ void transA_kernel(const float* __restrict__ xu2x_w) {
    __shared__ float tile[32][33];
    int bx = blockIdx.x * 32, by = blockIdx.y * 32;
    int tx = threadIdx.x, ty = threadIdx.y;  // 32 x 8
    #pragma unroll
    for (int r = 0; r < 4; r++)
        tile[ty + r * 8][tx] = xu2x_w[(by + ty + r * 8) * KIN + bx + tx];
    __syncthreads();
    #pragma unroll
    for (int r = 0; r < 4; r++)
        d_A[(bx + ty + r * 8) * NH + by + tx] = tile[tx][ty + r * 8];
}

// ---------------- prep2: Gp0, C0, x0, d_bar reset ----------------
__global__ void prep2_kernel(const float* __restrict__ y0,
                             const float* __restrict__ y2x_w,
                             const float* __restrict__ y2x_b,
                             const float* __restrict__ xu2x_w,
                             const float* __restrict__ x2y_w) {
    int idx = blockIdx.x * blockDim.x + threadIdx.x;
    int stride = gridDim.x * blockDim.x;
    if (idx == 0) d_bar = 0u;
    for (int t = idx; t < NU * NH; t += stride) {
        int u = t / NH, h = t % NH;
        d_Gp[u * NH + h] = xu2x_w[h * KIN + NH + u];
    }
    for (int t = idx; t < NH * NY; t += stride) {
        int h = t / NY, n = t % NY;
        d_Cbuf[h * (LCH * NY) + n] = x2y_w[n * NH + h];
    }
    for (int t = idx; t < BB * NH; t += stride) {
        int b = t / NH, h = t % NH;
        float acc = y2x_b[h];
        #pragma unroll 8
        for (int n = 0; n < NY; n++) acc += y0[b * NY + n] * y2x_w[h * NY + n];
        d_Xc[b * NH + h] = acc;
    }
}

// ---------------- svec: bias chains (coalesced via d_A / d_Cbuf) ----------------
__global__ void svec_kernel(const float* __restrict__ xu2x_b,
                            const float* __restrict__ x2y_b) {
    __shared__ float s[NH];
    int t = threadIdx.x;
    s[t] = 0.0f;
    __syncthreads();
    for (int j = 0; j < LCH; j++) {
        if (t < NY) {
            float acc = x2y_b[t];
            #pragma unroll 8
            for (int h = 0; h < NH; h++) acc += s[h] * d_Cbuf[h * (LCH * NY) + t];
            d_yb[j * NY + t] = acc;
        }
        float acc = xu2x_b[t];
        #pragma unroll 8
        for (int p = 0; p < NH; p++) acc += s[p] * d_A[p * NH + t];
        __syncthreads();
        s[t] = acc;
        __syncthreads();
    }
    d_bL[t] = s[t];
}

// ---------------- generic GEMM: C = A@B (+Add), tile 128x64, 128 threads ----------------
__global__ void __launch_bounds__(128) gemm_f(
    const float* __restrict__ A, long aBatch, int lda,
    const float* __restrict__ B, int ldb,
    const float* __restrict__ Add, long addBatch,
    float* __restrict__ C, long cBatch, int ldc, int K)
{
    __shared__ float As[2][16][132];
    __shared__ float Bs[2][16][68];
    int t = threadIdx.x;
    int col0 = blockIdx.x * 64;
    long q = blockIdx.y;
    int tx8 = (t & 7) * 8, ty8 = (t >> 3) * 8;

    const float* Arow = A + q * aBatch + (long)t * lda;
    int kbB = t >> 3, c8B = (t & 7) * 8;
    const float* Bbase = B + (long)kbB * ldb + col0 + c8B;

    ull acc[8][4];
    #pragma unroll
    for (int i = 0; i < 8; i++)
        #pragma unroll
        for (int jj = 0; jj < 4; jj++) acc[i][jj] = 0ull;

    float4 ra[4], rb0, rb1;
    #pragma unroll
    for (int h = 0; h < 4; h++) ra[h] = *(const float4*)(Arow + h * 4);
    rb0 = *(const float4*)(Bbase);
    rb1 = *(const float4*)(Bbase + 4);
    stsA16(As[0], t, ra);
    *(float4*)&Bs[0][kbB][c8B] = rb0;
    *(float4*)&Bs[0][kbB][c8B + 4] = rb1;
    __syncthreads();

    int KT = K >> 4;
    for (int kt = 0; kt < KT; kt++) {
        int cur = kt & 1;
        bool more = (kt + 1 < KT);
        if (more) {
            int k0 = (kt + 1) * 16;
            #pragma unroll
            for (int h = 0; h < 4; h++) ra[h] = *(const float4*)(Arow + k0 + h * 4);
            rb0 = *(const float4*)(Bbase + (long)k0 * ldb);
            rb1 = *(const float4*)(Bbase + (long)k0 * ldb + 4);
        }
        core8x8(As[cur], Bs[cur], ty8, tx8, acc);
        if (more) {
            stsA16(As[cur ^ 1], t, ra);
            *(float4*)&Bs[cur ^ 1][kbB][c8B] = rb0;
            *(float4*)&Bs[cur ^ 1][kbB][c8B + 4] = rb1;
        }
        __syncthreads();
    }

    #pragma unroll
    for (int e = 0; e < 8; e++) {
        int r = ty8 + e;
        float2 x0 = up2(acc[e][0]), x1 = up2(acc[e][1]);
        float2 x2 = up2(acc[e][2]), x3 = up2(acc[e][3]);
        float4 v0 = make_float4(x0.x, x0.y, x1.x, x1.y);
        float4 v1 = make_float4(x2.x, x2.y, x3.x, x3.y);
        long off = (long)r * ldc + col0 + tx8;
        if (Add != nullptr) {
            const float* ap = Add + q * addBatch + off;
            float4 a0 = *(const float4*)ap;
            float4 a1 = *(const float4*)(ap + 4);
            v0.x += a0.x; v0.y += a0.y; v0.z += a0.z; v0.w += a0.w;
            v1.x += a1.x; v1.y += a1.y; v1.z += a1.z; v1.w += a1.w;
        }
        float* cp = C + q * cBatch + off;
        *(float4*)cp = v0;
        *(float4*)(cp + 4) = v1;
    }
}

// ---------------- S32 = Uchunk @ Grev + bL ----------------
__global__ void __launch_bounds__(128) s32_kernel(const float* __restrict__ U) {
    __shared__ float As[2][16][132];
    __shared__ float Bs[2][16][68];
    int t = threadIdx.x;
    int col0 = blockIdx.x * 64;
    int q = blockIdx.y;
    int tx8 = (t & 7) * 8, ty8 = (t >> 3) * 8;

    long uBase = (long)q * (LCH * BB * NU) + (long)t * NU;
    int kbB = t >> 3, c8B = (t & 7) * 8;

    ull acc[8][4];
    #pragma unroll
    for (int i = 0; i < 8; i++)
        #pragma unroll
        for (int jj = 0; jj < 4; jj++) acc[i][jj] = 0ull;

    float4 ra[4], rb0, rb1;
    #pragma unroll
    for (int h = 0; h < 4; h++) {
        int k = h * 4;
        ra[h] = *(const float4*)(U + uBase + (long)(k >> 5) * (BB * NU) + (k & 31));
    }
    {
        const float* brow = d_Gp + (long)((31 - (kbB >> 5)) * NU + (kbB & 31)) * NH + col0 + c8B;
        rb0 = *(const float4*)brow;
        rb1 = *(const float4*)(brow + 4);
    }
    stsA16(As[0], t, ra);
    *(float4*)&Bs[0][kbB][c8B] = rb0;
    *(float4*)&Bs[0][kbB][c8B + 4] = rb1;
    __syncthreads();

    const int KT = (LCH * NU) >> 4;  // 64
    for (int kt = 0; kt < KT; kt++) {
        int cur = kt & 1;
        bool more = (kt + 1 < KT);
        if (more) {
            int k0 = (kt + 1) * 16;
            #pragma unroll
            for (int h = 0; h < 4; h++) {
                int k = k0 + h * 4;
                ra[h] = *(const float4*)(U + uBase + (long)(k >> 5) * (BB * NU) + (k & 31));
            }
            int kb = k0 + kbB;
            const float* brow = d_Gp + (long)((31 - (kb >> 5)) * NU + (kb & 31)) * NH + col0 + c8B;
            rb0 = *(const float4*)brow;
            rb1 = *(const float4*)(brow + 4);
        }
        core8x8(As[cur], Bs[cur], ty8, tx8, acc);
        if (more) {
            stsA16(As[cur ^ 1], t, ra);
            *(float4*)&Bs[cur ^ 1][kbB][c8B] = rb0;
            *(float4*)&Bs[cur ^ 1][kbB][c8B + 4] = rb1;
        }
        __syncthreads();
    }

    float4 bl0 = *(const float4*)&d_bL[col0 + tx8];
    float4 bl1 = *(const float4*)&d_bL[col0 + tx8 + 4];
    #pragma unroll
    for (int e = 0; e < 8; e++) {
        int r = ty8 + e;
        float2 x0 = up2(acc[e][0]), x1 = up2(acc[e][1]);
        float2 x2 = up2(acc[e][2]), x3 = up2(acc[e][3]);
        float4 v0 = make_float4(x0.x + bl0.x, x0.y + bl0.y, x1.x + bl0.z, x1.y + bl0.w);
        float4 v1 = make_float4(x2.x + bl1.x, x2.y + bl1.y, x3.x + bl1.z, x3.y + bl1.w);
        float* cp = d_S32 + (long)q * CH + (long)r * NH + col0 + tx8;
        *(float4*)cp = v0;
        *(float4*)(cp + 4) = v1;
    }
}

// ---------------- persistent sequential chain: 16 steps of A^128 ----------------
// grid = 32 blocks (8 col-tiles x 4 row-tiles), 128 threads, tile 32x64
__global__ void __launch_bounds__(128) seq_persist() {
    __shared__ float As[2][16][36];
    __shared__ float Bs[2][16][68];
    int t = threadIdx.x;
    int col0 = (blockIdx.x & 7) * 64;
    int row0 = (blockIdx.x >> 3) * 32;
    int tx8 = (t & 7) * 8;
    int ty2 = (t >> 3) * 2;

    int rA = t >> 2, kqA = (t & 3) * 4;
    int kbB = t >> 3, c8B = (t & 7) * 8;
    const float* W = d_Pow[6];
    const float* Bbase = W + (long)kbB * NH + col0 + c8B;

    for (int p = 0; p < PCH / 4; p++) {
        const float* X = d_Xc + 4L * p * CH;
        const float* Sp = d_S128 + (long)p * CH;
        float* D = d_Xc + 4L * (p + 1) * CH;
        const float* Axrow = X + (long)(row0 + rA) * NH;

        ull acc[2][4];
        #pragma unroll
        for (int i = 0; i < 2; i++)
            #pragma unroll
            for (int jj = 0; jj < 4; jj++) acc[i][jj] = 0ull;

        float4 ra, rb0, rb1;
        ra = __ldcg((const float4*)(Axrow + kqA));
        rb0 = *(const float4*)Bbase;
        rb1 = *(const float4*)(Bbase + 4);
        As[0][kqA + 0][rA] = ra.x; As[0][kqA + 1][rA] = ra.y;
        As[0][kqA + 2][rA] = ra.z; As[0][kqA + 3][rA] = ra.w;
        *(float4*)&Bs[0][kbB][c8B] = rb0;
        *(float4*)&Bs[0][kbB][c8B + 4] = rb1;
        __syncthreads();

        const int KT = NH >> 4;  // 32
        for (int kt = 0; kt < KT; kt++) {
            int cur = kt & 1;
            bool more = (kt + 1 < KT);
            if (more) {
                int k0 = (kt + 1) * 16;
                ra = __ldcg((const float4*)(Axrow + k0 + kqA));
                rb0 = *(const float4*)(Bbase + (long)k0 * NH);
                rb1 = *(const float4*)(Bbase + (long)k0 * NH + 4);
            }
            #pragma unroll
            for (int k = 0; k < 16; k++) {
                float2 a = *(const float2*)&As[cur][k][ty2];
                ulonglong2 b0 = *(const ulonglong2*)&Bs[cur][k][tx8];
                ulonglong2 b1 = *(const ulonglong2*)&Bs[cur][k][tx8 + 4];
                ull p0 = pk2(a.x), p1 = pk2(a.y);
                fma2(acc[0][0], p0, b0.x); fma2(acc[0][1], p0, b0.y);
                fma2(acc[0][2], p0, b1.x); fma2(acc[0][3], p0, b1.y);
                fma2(acc[1][0], p1, b0.x); fma2(acc[1][1], p1, b0.y);
                fma2(acc[1][2], p1, b1.x); fma2(acc[1][3], p1, b1.y);
            }
            if (more) {
                As[cur ^ 1][kqA + 0][rA] = ra.x; As[cur ^ 1][kqA + 1][rA] = ra.y;
                As[cur ^ 1][kqA + 2][rA] = ra.z; As[cur ^ 1][kqA + 3][rA] = ra.w;
                *(float4*)&Bs[cur ^ 1][kbB][c8B] = rb0;
                *(float4*)&Bs[cur ^ 1][kbB][c8B + 4] = rb1;
            }
            __syncthreads();
        }

        #pragma unroll
        for (int e = 0; e < 2; e++) {
            int r = row0 + ty2 + e;
            float2 x0 = up2(acc[e][0]), x1 = up2(acc[e][1]);
            float2 x2 = up2(acc[e][2]), x3 = up2(acc[e][3]);
            const float* ap = Sp + (long)r * NH + col0 + tx8;
            float4 a0 = __ldcg((const float4*)ap);
            float4 a1 = __ldcg((const float4*)(ap + 4));
            float4 v0 = make_float4(x0.x + a0.x, x0.y + a0.y, x1.x + a0.z, x1.y + a0.w);
            float4 v1 = make_float4(x2.x + a1.x, x2.y + a1.y, x3.x + a1.z, x3.y + a1.w);
            float* dp = D + (long)r * NH + col0 + tx8;
            *(float4*)dp = v0;
            *(float4*)(dp + 4) = v1;
        }

        // grid barrier
        __threadfence();
        __syncthreads();
        if (t == 0) {
            atomicAdd(&d_bar, 1u);
            unsigned target = 32u * (unsigned)(p + 1);
            while (atomicAdd(&d_bar, 0u) < target) {}
        }
        __syncthreads();
    }
}

// ---------------- output pass ----------------
__global__ void __launch_bounds__(128) out_kernel(const float* __restrict__ U,
                                                  float* __restrict__ out) {
    __shared__ float As[2][16][132];
    __shared__ float Bs[2][16][68];
    int pj = blockIdx.x;
    int p = pj >> 5, j = pj & 31;
    int t = threadIdx.x;
    int KT = 32 + 2 * j;
    int tx8 = (t & 7) * 8, ty8 = (t >> 3) * 8;

    const float* xcRow = d_Xc + (long)p * CH + (long)t * NH;
    long uBase = (long)p * (LCH * BB * NU) + (long)t * NU;
    int kbB = t >> 3, c8B = (t & 7) * 8;

    ull acc[8][4];
    #pragma unroll
    for (int i = 0; i < 8; i++)
        #pragma unroll
        for (int jj = 0; jj < 4; jj++) acc[i][jj] = 0ull;

    float4 ra[4], rb0, rb1;
    #pragma unroll
    for (int h = 0; h < 4; h++) ra[h] = *(const float4*)(xcRow + h * 4);
    {
        const float* brow = d_Cbuf + (long)kbB * (LCH * NY) + j * NY + c8B;
        rb0 = *(const float4*)brow;
        rb1 = *(const float4*)(brow + 4);
    }
    stsA16(As[0], t, ra);
    *(float4*)&Bs[0][kbB][c8B] = rb0;
    *(float4*)&Bs[0][kbB][c8B + 4] = rb1;
    __syncthreads();

    for (int kt = 0; kt < KT; kt++) {
        int cur = kt & 1;
        bool more = (kt + 1 < KT);
        if (more) {
            int k0 = (kt + 1) * 16;
            if (k0 < NH) {
                #pragma unroll
                for (int h = 0; h < 4; h++) ra[h] = *(const float4*)(xcRow + k0 + h * 4);
            } else {
                int kc = k0 - NH;
                #pragma unroll
                for (int h = 0; h < 4; h++) {
                    int k = kc + h * 4;
                    ra[h] = *(const float4*)(U + uBase + (long)(k >> 5) * (BB * NU) + (k & 31));
                }
            }
            int kb = k0 + kbB;
            const float* brow;
            if (kb < NH) {
                brow = d_Cbuf + (long)kb * (LCH * NY) + j * NY + c8B;
            } else {
                int kc = kb - NH;
                brow = d_Hd + (long)((j - 1 - (kc >> 5)) * NU + (kc & 31)) * NY + c8B;
            }
            rb0 = *(const float4*)brow;
            rb1 = *(const float4*)(brow + 4);
        }
        core8x8(As[cur], Bs[cur], ty8, tx8, acc);
        if (more) {
            stsA16(As[cur ^ 1], t, ra);
            *(float4*)&Bs[cur ^ 1][kbB][c8B] = rb0;
            *(float4*)&Bs[cur ^ 1][kbB][c8B + 4] = rb1;
        }
        __syncthreads();
    }

    float4 yb0 = *(const float4*)(d_yb + j * NY + tx8);
    float4 yb1 = *(const float4*)(d_yb + j * NY + tx8 + 4);
    float* obase = out + (long)pj * (BB * NY);
    #pragma unroll
    for (int e = 0; e < 8; e++) {
        int r = ty8 + e;
        float2 x0 = up2(acc[e][0]), x1 = up2(acc[e][1]);
        float2 x2 = up2(acc[e][2]), x3 = up2(acc[e][3]);
        float4 v0 = make_float4(x0.x + yb0.x, x0.y + yb0.y, x1.x + yb0.z, x1.y + yb0.w);
        float4 v1 = make_float4(x2.x + yb1.x, x2.y + yb1.y, x3.x + yb1.z, x3.y + yb1.w);
        float* op = obase + (long)r * NY + tx8;
        *(float4*)op = v0;
        *(float4*)(op + 4) = v1;
    }
}

// ---------------- small GEMM (tiny Gp chain steps) ----------------
__global__ void gemm_small(const float* __restrict__ A, const float* __restrict__ B,
                           float* __restrict__ C, int K, int lda, int ldb, int ldc) {
    __shared__ float As[32][33];
    __shared__ float Bs[32][33];
    int tid = threadIdx.x;
    int tx = tid & 15, ty = tid >> 4;
    int row0 = blockIdx.y * 32, col0 = blockIdx.x * 32;
    float a00 = 0.f, a01 = 0.f, a10 = 0.f, a11 = 0.f;
    for (int k0 = 0; k0 < K; k0 += 32) {
        #pragma unroll
        for (int r = 0; r < 4; r++) {
            int e = tid + 256 * r;
            int ar = e >> 5, ac = e & 31;
            As[ar][ac] = A[(row0 + ar) * lda + k0 + ac];
            Bs[ar][ac] = B[(k0 + ar) * ldb + col0 + ac];
        }
        __syncthreads();
        #pragma unroll
        for (int k = 0; k < 32; k++) {
            float x0 = As[ty * 2 + 0][k], x1 = As[ty * 2 + 1][k];
            float w0 = Bs[k][tx * 2 + 0], w1 = Bs[k][tx * 2 + 1];
            a00 += x0 * w0; a01 += x0 * w1;
            a10 += x1 * w0; a11 += x1 * w1;
        }
        __syncthreads();
    }
    int r = row0 + ty * 2, c = col0 + tx * 2;
    C[r * ldc + c] = a00;       C[r * ldc + c + 1] = a01;
    C[(r + 1) * ldc + c] = a10; C[(r + 1) * ldc + c + 1] = a11;
}

// ---------------- host ----------------
extern "C" void kernel_launch(void* const* d_in, const int* in_sizes, int n_in,
                              void* d_out, int out_size) {
    const float* y0     = (const float*)d_in[0];
    const float* U      = (const float*)d_in[1];
    const float* y2x_w  = (const float*)d_in[2];
    const float* y2x_b  = (const float*)d_in[3];
    const float* xu2x_w = (const float*)d_in[4];
    const float* xu2x_b = (const float*)d_in[5];
    const float* x2y_w  = (const float*)d_in[6];
    const float* x2y_b  = (const float*)d_in[7];
    float* out = (float*)d_out;

    float *pA, *pP, *pCbuf, *pGp, *pHd, *pXc, *pS32, *pS64, *pS128;
    cudaGetSymbolAddress((void**)&pA, d_A);
    cudaGetSymbolAddress((void**)&pP, d_Pow);
    cudaGetSymbolAddress((void**)&pCbuf, d_Cbuf);
    cudaGetSymbolAddress((void**)&pGp, d_Gp);
    cudaGetSymbolAddress((void**)&pHd, d_Hd);
    cudaGetSymbolAddress((void**)&pXc, d_Xc);
    cudaGetSymbolAddress((void**)&pS32, d_S32);
    cudaGetSymbolAddress((void**)&pS64, d_S64);
    cudaGetSymbolAddress((void**)&pS128, d_S128);
    const long SZ = NH * NH;

    transA_kernel<<<dim3(16, 16), dim3(32, 8)>>>(xu2x_w);
    prep2_kernel<<<128, 256>>>(y0, y2x_w, y2x_b, xu2x_w, x2y_w);
    svec_kernel<<<1, NH>>>(xu2x_b, x2y_b);

    // A^2 .. A^128 by squaring
    gemm_f<<<dim3(8, 4), 128>>>(pA, 128L * NH, NH, pA, NH, nullptr, 0, pP, 128L * NH, NH, NH);
    for (int k = 1; k < 7; k++)
        gemm_f<<<dim3(8, 4), 128>>>(pP + (k - 1) * SZ, 128L * NH, NH,
                                    pP + (k - 1) * SZ, NH, nullptr, 0,
                                    pP + k * SZ, 128L * NH, NH, NH);

    // C_j doubling: C[j+2^k] = A^{2^k} @ C[j], j < 2^k
    for (int k = 0; k < 5; k++) {
        const float* mult = (k == 0) ? pA : (pP + (k - 1) * SZ);
        int w = NY << k;  // columns already present
        gemm_f<<<dim3(w / 64, 4), 128>>>(mult, 128L * NH, NH,
                                         pCbuf, LCH * NY, nullptr, 0,
                                         pCbuf + w, 128L * (LCH * NY), LCH * NY, NH);
    }
    // G'_d doubling
    for (int k = 0; k < 2; k++) {
        const float* mult = (k == 0) ? pA : (pP + (k - 1) * SZ);
        int rows = NU << k;  // 32, 64
        gemm_small<<<dim3(16, rows / 32), 256>>>(pGp, mult, pGp + rows * NH, NH, NH, NH, NH);
    }
    for (int k = 2; k < 5; k++) {
        const float* mult = pP + (k - 1) * SZ;
        int rows = NU << k;  // 128, 256, 512
        gemm_f<<<dim3(8, rows / 128), 128>>>(pGp, 128L * NH, NH, mult, NH, nullptr, 0,
                                             pGp + rows * NH, 128L * NH, NH, NH);
    }
    // Hd = Gp @ C_0   (1024 rows x 64)
    gemm_f<<<dim3(1, 8), 128>>>(pGp, 128L * NH, NH, pCbuf, LCH * NY, nullptr, 0,
                                pHd, 128L * NY, NY, NH);

    // S32 per chunk
    s32_kernel<<<dim3(NH / 64, PCH), 128>>>(U);
    // S64[p] = S32[2p] @ A^32 + S32[2p+1]
    gemm_f<<<dim3(8, PCH / 2), 128>>>(pS32, 2L * CH, NH, pP + 4 * SZ, NH,
                                      pS32 + CH, 2L * CH, pS64, CH, NH, NH);
    // S128[r] = S64[2r] @ A^64 + S64[2r+1]
    gemm_f<<<dim3(8, PCH / 4), 128>>>(pS64, 2L * CH, NH, pP + 5 * SZ, NH,
                                      pS64 + CH, 2L * CH, pS128, CH, NH, NH);

    // 16 sequential steps of A^128 in one persistent kernel
    seq_persist<<<32, 128>>>();

    // fill c+2 states: Xc[4r+2] = Xc[4r] @ A^64 + S64[2r]
    gemm_f<<<dim3(8, PCH / 4), 128>>>(pXc, 4L * CH, NH, pP + 5 * SZ, NH,
                                      pS64, 2L * CH, pXc + 2L * CH, 4L * CH, NH, NH);
    // fill odd states: Xc[2m+1] = Xc[2m] @ A^32 + S32[2m]
    gemm_f<<<dim3(8, PCH / 2), 128>>>(pXc, 2L * CH, NH, pP + 4 * SZ, NH,
                                      pS32, 2L * CH, pXc + CH, 2L * CH, NH, NH);

    // output pass: 2049 (p,j) tiles
    out_kernel<<<PCH * LCH + 1, 128>>>(U, out);

    (void)in_sizes; (void)n_in; (void)out_size;
}

// round 5
// speedup vs baseline: 3.4752x; 1.0293x over previous
#include <cuda_runtime.h>
#include <cstdint>

#define NY 64
#define NU 32
#define NH 512
#define BB 128
#define LCH 32
#define PCH 64
#define KIN 544   // NH + NU
#define CH (BB * NH)
#define LDCB (LCH * NY)   // 2048, Cbuf row stride

typedef unsigned long long ull;

// ---------------- device scratch ----------------
__device__ float d_A[NH * NH];
__device__ float d_Pow[8][NH * NH];          // A^2,4,8,16,32,64,128,256
__device__ float d_Cbuf[NH * LCH * NY];      // [512][2048] col block j = A^j Wy^T
__device__ float d_Gp[LCH * NU * NH];        // [1024][512] row block d = Bm A^d
__device__ float d_Hd[LCH * NU * NY];        // [32][32][64]
__device__ float d_yb[LCH * NY];
__device__ float d_bL[NH];
__device__ float d_Xc[(PCH + 1) * CH];
__device__ float d_S32[PCH * CH];
__device__ float d_S64[(PCH / 2) * CH];
__device__ float d_S128[(PCH / 4) * CH];
__device__ float d_S256[(PCH / 8) * CH];
__device__ unsigned d_bar;

// ---------------- f32x2 helpers ----------------
__device__ __forceinline__ ull pk2(float x) {
    ull r;
    asm("mov.b64 %0, {%1, %1};" : "=l"(r) : "f"(x));
    return r;
}
__device__ __forceinline__ void fma2(ull& d, ull a, ull b) {
    asm("fma.rn.f32x2 %0, %1, %2, %0;" : "+l"(d) : "l"(a), "l"(b));
}
__device__ __forceinline__ float2 up2(ull v) {
    float2 f;
    asm("mov.b64 {%0, %1}, %2;" : "=f"(f.x), "=f"(f.y) : "l"(v));
    return f;
}

// ---------------- shared 8x8 core on duplicated-A smem ----------------
// As rows: [k][m] each entry = packed (a,a). Bs: [k][n] floats.
__device__ __forceinline__ void core16d(const ull (*As)[132], const float (*Bs)[68],
                                        int ty8, int tx8, ull acc[8][4]) {
    #pragma unroll
    for (int k = 0; k < 16; k++) {
        ulonglong2 aA = *(const ulonglong2*)&As[k][ty8];
        ulonglong2 aB = *(const ulonglong2*)&As[k][ty8 + 2];
        ulonglong2 aC = *(const ulonglong2*)&As[k][ty8 + 4];
        ulonglong2 aD = *(const ulonglong2*)&As[k][ty8 + 6];
        ulonglong2 b0 = *(const ulonglong2*)&Bs[k][tx8];
        ulonglong2 b1 = *(const ulonglong2*)&Bs[k][tx8 + 4];
        fma2(acc[0][0], aA.x, b0.x); fma2(acc[0][1], aA.x, b0.y);
        fma2(acc[0][2], aA.x, b1.x); fma2(acc[0][3], aA.x, b1.y);
        fma2(acc[1][0], aA.y, b0.x); fma2(acc[1][1], aA.y, b0.y);
        fma2(acc[1][2], aA.y, b1.x); fma2(acc[1][3], aA.y, b1.y);
        fma2(acc[2][0], aB.x, b0.x); fma2(acc[2][1], aB.x, b0.y);
        fma2(acc[2][2], aB.x, b1.x); fma2(acc[2][3], aB.x, b1.y);
        fma2(acc[3][0], aB.y, b0.x); fma2(acc[3][1], aB.y, b0.y);
        fma2(acc[3][2], aB.y, b1.x); fma2(acc[3][3], aB.y, b1.y);
        fma2(acc[4][0], aC.x, b0.x); fma2(acc[4][1], aC.x, b0.y);
        fma2(acc[4][2], aC.x, b1.x); fma2(acc[4][3], aC.x, b1.y);
        fma2(acc[5][0], aC.y, b0.x); fma2(acc[5][1], aC.y, b0.y);
        fma2(acc[5][2], aC.y, b1.x); fma2(acc[5][3], aC.y, b1.y);
        fma2(acc[6][0], aD.x, b0.x); fma2(acc[6][1], aD.x, b0.y);
        fma2(acc[6][2], aD.x, b1.x); fma2(acc[6][3], aD.x, b1.y);
        fma2(acc[7][0], aD.y, b0.x); fma2(acc[7][1], aD.y, b0.y);
        fma2(acc[7][2], aD.y, b1.x); fma2(acc[7][3], aD.y, b1.y);
    }
}

__device__ __forceinline__ void stsAdup(ull (*As)[132], int t, const float4* ra) {
    #pragma unroll
    for (int h = 0; h < 4; h++) {
        As[h * 4 + 0][t] = pk2(ra[h].x);
        As[h * 4 + 1][t] = pk2(ra[h].y);
        As[h * 4 + 2][t] = pk2(ra[h].z);
        As[h * 4 + 3][t] = pk2(ra[h].w);
    }
}

// ---------------- generic 128x64 tile GEMM (A row-major plain) ----------------
__device__ __forceinline__ void gtile(ull (*As)[132], float (*Bs)[68],
                                      const float* __restrict__ A, int lda,
                                      const float* __restrict__ B, int ldb,
                                      float* __restrict__ C, int ldc,
                                      const float* __restrict__ Add, int K) {
    int t = threadIdx.x;
    int tx8 = (t & 7) * 8, ty8 = (t >> 3) * 8;
    const float* Arow = A + (long)t * lda;
    int kbB = t >> 3, c8B = (t & 7) * 8;
    const float* Bb = B + (long)kbB * ldb + c8B;

    ull acc[8][4];
    #pragma unroll
    for (int i = 0; i < 8; i++)
        #pragma unroll
        for (int jj = 0; jj < 4; jj++) acc[i][jj] = 0ull;

    float4 ra[4], rb0, rb1;
    #pragma unroll
    for (int h = 0; h < 4; h++) ra[h] = *(const float4*)(Arow + h * 4);
    rb0 = *(const float4*)Bb;
    rb1 = *(const float4*)(Bb + 4);
    stsAdup(As, t, ra);
    *(float4*)&Bs[kbB][c8B] = rb0;
    *(float4*)&Bs[kbB][c8B + 4] = rb1;
    __syncthreads();

    int KT = K >> 4;
    for (int kt = 0; kt < KT; kt++) {
        int cur = kt & 1;
        bool more = (kt + 1 < KT);
        if (more) {
            int k0 = (kt + 1) * 16;
            #pragma unroll
            for (int h = 0; h < 4; h++) ra[h] = *(const float4*)(Arow + k0 + h * 4);
            rb0 = *(const float4*)(Bb + (long)k0 * ldb);
            rb1 = *(const float4*)(Bb + (long)k0 * ldb + 4);
        }
        core16d(As + cur * 16, Bs + cur * 16, ty8, tx8, acc);
        if (more) {
            stsAdup(As + (cur ^ 1) * 16, t, ra);
            *(float4*)&Bs[(cur ^ 1) * 16 + kbB][c8B] = rb0;
            *(float4*)&Bs[(cur ^ 1) * 16 + kbB][c8B + 4] = rb1;
        }
        __syncthreads();
    }

    #pragma unroll
    for (int e = 0; e < 8; e++) {
        float2 x0 = up2(acc[e][0]), x1 = up2(acc[e][1]);
        float2 x2 = up2(acc[e][2]), x3 = up2(acc[e][3]);
        float4 v0 = make_float4(x0.x, x0.y, x1.x, x1.y);
        float4 v1 = make_float4(x2.x, x2.y, x3.x, x3.y);
        long off = (long)(ty8 + e) * ldc + tx8;
        if (Add != nullptr) {
            const float* ap = Add + off;
            float4 a0 = *(const float4*)ap;
            float4 a1 = *(const float4*)(ap + 4);
            v0.x += a0.x; v0.y += a0.y; v0.z += a0.z; v0.w += a0.w;
            v1.x += a1.x; v1.y += a1.y; v1.z += a1.z; v1.w += a1.w;
        }
        float* cp = C + off;
        *(float4*)cp = v0;
        *(float4*)(cp + 4) = v1;
    }
}

// ---------------- batched GEMM wrapper: C[q] = A[q]@B + Add[q] ----------------
__global__ void __launch_bounds__(128) gemm_f(
    const float* __restrict__ A, long aBatch, int lda,
    const float* __restrict__ B, int ldb,
    const float* __restrict__ Add, long addBatch,
    float* __restrict__ C, long cBatch, int ldc, int K) {
    __shared__ ull As[32][132];
    __shared__ float Bs[32][68];
    long q = blockIdx.y;
    int col0 = blockIdx.x * 64;
    gtile(As, Bs, A + q * aBatch, lda, B + col0, ldb, C + q * cBatch + col0, ldc,
          Add ? Add + q * addBatch + col0 : (const float*)nullptr, K);
}

// ---------------- precompute level kernel ----------------
// lvl 1..8. Per level runs concurrently: Pow[lvl-1]=Mprev^2 (32 blk);
// lvl<=5: Cbuf doubling (4*2^(lvl-1) blk) + Gp doubling (8*rowTiles blk);
// lvl==6: Hd = Gp @ C0 (8 blk).
__global__ void __launch_bounds__(128) mgemm_kernel(int lvl) {
    __shared__ ull As[32][132];
    __shared__ float Bs[32][68];
    int bx = blockIdx.x;
    const float* Mprev = (lvl == 1) ? d_A : d_Pow[lvl - 2];

    if (bx < 32) {
        int row0 = (bx >> 3) * 128, col0 = (bx & 7) * 64;
        gtile(As, Bs, Mprev + (long)row0 * NH, NH, Mprev + col0, NH,
              d_Pow[lvl - 1] + (long)row0 * NH + col0, NH, nullptr, NH);
        return;
    }
    bx -= 32;
    if (lvl <= 5) {
        int colTiles = 1 << (lvl - 1);
        int cbBlocks = 4 * colTiles;
        if (bx < cbBlocks) {
            int rowTile = bx / colTiles, colTile = bx % colTiles;
            int row0 = rowTile * 128;
            gtile(As, Bs, Mprev + (long)row0 * NH, NH,
                  d_Cbuf + colTile * 64, LDCB,
                  d_Cbuf + (long)row0 * LDCB + (64 << (lvl - 1)) + colTile * 64, LDCB,
                  nullptr, NH);
            return;
        }
        bx -= cbBlocks;
        // Gp doubling with overshooting 128-row tiles (garbage rows overwritten later)
        int rowTile = bx >> 3, colTile = bx & 7;
        int row0in = rowTile * 128;
        int shift = 32 << (lvl - 1);
        gtile(As, Bs, d_Gp + (long)row0in * NH, NH, Mprev + colTile * 64, NH,
              d_Gp + (long)(row0in + shift) * NH + colTile * 64, NH, nullptr, NH);
        return;
    }
    if (lvl == 6) {
        // Hd = Gp @ C0, 8 row tiles
        int rowTile = bx;
        gtile(As, Bs, d_Gp + (long)rowTile * 128 * NH, NH, d_Cbuf, LDCB,
              d_Hd + (long)rowTile * 128 * NY, NY, nullptr, NH);
    }
}

// ---------------- transpose A ----------------
__global__ void transA_kernel(const float* __restrict__ xu2x_w) {
    __shared__ float tile[32][33];
    int bx = blockIdx.x * 32, by = blockIdx.y * 32;
    int tx = threadIdx.x, ty = threadIdx.y;  // 32 x 8
    #pragma unroll
    for (int r = 0; r < 4; r++)
        tile[ty + r * 8][tx] = xu2x_w[(by + ty + r * 8) * KIN + bx + tx];
    __syncthreads();
    #pragma unroll
    for (int r = 0; r < 4; r++)
        d_A[(bx + ty + r * 8) * NH + by + tx] = tile[tx][ty + r * 8];
}

// ---------------- prep2: Gp0, C0, x0, barrier reset ----------------
__global__ void prep2_kernel(const float* __restrict__ y0,
                             const float* __restrict__ y2x_w,
                             const float* __restrict__ y2x_b,
                             const float* __restrict__ xu2x_w,
                             const float* __restrict__ x2y_w) {
    int idx = blockIdx.x * blockDim.x + threadIdx.x;
    int stride = gridDim.x * blockDim.x;
    if (idx == 0) d_bar = 0u;
    for (int t = idx; t < NU * NH; t += stride) {
        int u = t / NH, h = t % NH;
        d_Gp[u * NH + h] = xu2x_w[h * KIN + NH + u];
    }
    for (int t = idx; t < NH * NY; t += stride) {
        int h = t / NY, n = t % NY;
        d_Cbuf[h * LDCB + n] = x2y_w[n * NH + h];
    }
    for (int t = idx; t < BB * NH; t += stride) {
        int b = t / NH, h = t % NH;
        float acc = y2x_b[h];
        #pragma unroll 8
        for (int n = 0; n < NY; n++) acc += y0[b * NY + n] * y2x_w[h * NY + n];
        d_Xc[b * NH + h] = acc;
    }
}

// ---------------- svec: bias chains ----------------
__global__ void svec_kernel(const float* __restrict__ xu2x_b,
                            const float* __restrict__ x2y_b) {
    __shared__ float s[NH];
    int t = threadIdx.x;
    s[t] = 0.0f;
    __syncthreads();
    for (int j = 0; j < LCH; j++) {
        if (t < NY) {
            float acc = x2y_b[t];
            #pragma unroll 8
            for (int h = 0; h < NH; h++) acc += s[h] * d_Cbuf[h * LDCB + t];
            d_yb[j * NY + t] = acc;
        }
        float acc = xu2x_b[t];
        #pragma unroll 8
        for (int p = 0; p < NH; p++) acc += s[p] * d_A[p * NH + t];
        __syncthreads();
        s[t] = acc;
        __syncthreads();
    }
    d_bL[t] = s[t];
}

// ---------------- S32 = Uchunk @ Grev + bL ----------------
__global__ void __launch_bounds__(128) s32_kernel(const float* __restrict__ U) {
    __shared__ ull As[32][132];
    __shared__ float Bs[32][68];
    int t = threadIdx.x;
    int col0 = blockIdx.x * 64;
    int q = blockIdx.y;
    int tx8 = (t & 7) * 8, ty8 = (t >> 3) * 8;

    long uBase = (long)q * (LCH * BB * NU) + (long)t * NU;
    int kbB = t >> 3, c8B = (t & 7) * 8;

    ull acc[8][4];
    #pragma unroll
    for (int i = 0; i < 8; i++)
        #pragma unroll
        for (int jj = 0; jj < 4; jj++) acc[i][jj] = 0ull;

    float4 ra[4], rb0, rb1;
    #pragma unroll
    for (int h = 0; h < 4; h++) {
        int k = h * 4;
        ra[h] = *(const float4*)(U + uBase + (long)(k >> 5) * (BB * NU) + (k & 31));
    }
    {
        const float* brow = d_Gp + (long)((31 - (kbB >> 5)) * NU + (kbB & 31)) * NH + col0 + c8B;
        rb0 = *(const float4*)brow;
        rb1 = *(const float4*)(brow + 4);
    }
    stsAdup(As, t, ra);
    *(float4*)&Bs[kbB][c8B] = rb0;
    *(float4*)&Bs[kbB][c8B + 4] = rb1;
    __syncthreads();

    const int KT = (LCH * NU) >> 4;  // 64
    for (int kt = 0; kt < KT; kt++) {
        int cur = kt & 1;
        bool more = (kt + 1 < KT);
        if (more) {
            int k0 = (kt + 1) * 16;
            #pragma unroll
            for (int h = 0; h < 4; h++) {
                int k = k0 + h * 4;
                ra[h] = *(const float4*)(U + uBase + (long)(k >> 5) * (BB * NU) + (k & 31));
            }
            int kb = k0 + kbB;
            const float* brow = d_Gp + (long)((31 - (kb >> 5)) * NU + (kb & 31)) * NH + col0 + c8B;
            rb0 = *(const float4*)brow;
            rb1 = *(const float4*)(brow + 4);
        }
        core16d(As + cur * 16, Bs + cur * 16, ty8, tx8, acc);
        if (more) {
            stsAdup(As + (cur ^ 1) * 16, t, ra);
            *(float4*)&Bs[(cur ^ 1) * 16 + kbB][c8B] = rb0;
            *(float4*)&Bs[(cur ^ 1) * 16 + kbB][c8B + 4] = rb1;
        }
        __syncthreads();
    }

    float4 bl0 = *(const float4*)&d_bL[col0 + tx8];
    float4 bl1 = *(const float4*)&d_bL[col0 + tx8 + 4];
    #pragma unroll
    for (int e = 0; e < 8; e++) {
        int r = ty8 + e;
        float2 x0 = up2(acc[e][0]), x1 = up2(acc[e][1]);
        float2 x2 = up2(acc[e][2]), x3 = up2(acc[e][3]);
        float4 v0 = make_float4(x0.x + bl0.x, x0.y + bl0.y, x1.x + bl0.z, x1.y + bl0.w);
        float4 v1 = make_float4(x2.x + bl1.x, x2.y + bl1.y, x3.x + bl1.z, x3.y + bl1.w);
        float* cp = d_S32 + (long)q * CH + (long)r * NH + col0 + tx8;
        *(float4*)cp = v0;
        *(float4*)(cp + 4) = v1;
    }
}

// ---------------- persistent sequential chain: 8 steps of A^256 ----------------
__global__ void __launch_bounds__(128) seq_persist() {
    __shared__ float As[2][16][36];
    __shared__ float Bs[2][16][68];
    int t = threadIdx.x;
    int col0 = (blockIdx.x & 7) * 64;
    int row0 = (blockIdx.x >> 3) * 32;
    int tx8 = (t & 7) * 8;
    int ty2 = (t >> 3) * 2;

    int rA = t >> 2, kqA = (t & 3) * 4;
    int kbB = t >> 3, c8B = (t & 7) * 8;
    const float* W = d_Pow[7];
    const float* Bbase = W + (long)kbB * NH + col0 + c8B;

    for (int p = 0; p < PCH / 8; p++) {
        const float* X = d_Xc + 8L * p * CH;
        const float* Sp = d_S256 + (long)p * CH;
        float* D = d_Xc + 8L * (p + 1) * CH;
        const float* Axrow = X + (long)(row0 + rA) * NH;

        ull acc[2][4];
        #pragma unroll
        for (int i = 0; i < 2; i++)
            #pragma unroll
            for (int jj = 0; jj < 4; jj++) acc[i][jj] = 0ull;

        float4 ra, rb0, rb1;
        ra = __ldcg((const float4*)(Axrow + kqA));
        rb0 = *(const float4*)Bbase;
        rb1 = *(const float4*)(Bbase + 4);
        As[0][kqA + 0][rA] = ra.x; As[0][kqA + 1][rA] = ra.y;
        As[0][kqA + 2][rA] = ra.z; As[0][kqA + 3][rA] = ra.w;
        *(float4*)&Bs[0][kbB][c8B] = rb0;
        *(float4*)&Bs[0][kbB][c8B + 4] = rb1;
        __syncthreads();

        const int KT = NH >> 4;  // 32
        for (int kt = 0; kt < KT; kt++) {
            int cur = kt & 1;
            bool more = (kt + 1 < KT);
            if (more) {
                int k0 = (kt + 1) * 16;
                ra = __ldcg((const float4*)(Axrow + k0 + kqA));
                rb0 = *(const float4*)(Bbase + (long)k0 * NH);
                rb1 = *(const float4*)(Bbase + (long)k0 * NH + 4);
            }
            #pragma unroll
            for (int k = 0; k < 16; k++) {
                float2 a = *(const float2*)&As[cur][k][ty2];
                ulonglong2 b0 = *(const ulonglong2*)&Bs[cur][k][tx8];
                ulonglong2 b1 = *(const ulonglong2*)&Bs[cur][k][tx8 + 4];
                ull p0 = pk2(a.x), p1 = pk2(a.y);
                fma2(acc[0][0], p0, b0.x); fma2(acc[0][1], p0, b0.y);
                fma2(acc[0][2], p0, b1.x); fma2(acc[0][3], p0, b1.y);
                fma2(acc[1][0], p1, b0.x); fma2(acc[1][1], p1, b0.y);
                fma2(acc[1][2], p1, b1.x); fma2(acc[1][3], p1, b1.y);
            }
            if (more) {
                As[cur ^ 1][kqA + 0][rA] = ra.x; As[cur ^ 1][kqA + 1][rA] = ra.y;
                As[cur ^ 1][kqA + 2][rA] = ra.z; As[cur ^ 1][kqA + 3][rA] = ra.w;
                *(float4*)&Bs[cur ^ 1][kbB][c8B] = rb0;
                *(float4*)&Bs[cur ^ 1][kbB][c8B + 4] = rb1;
            }
            __syncthreads();
        }

        #pragma unroll
        for (int e = 0; e < 2; e++) {
            int r = row0 + ty2 + e;
            float2 x0 = up2(acc[e][0]), x1 = up2(acc[e][1]);
            float2 x2 = up2(acc[e][2]), x3 = up2(acc[e][3]);
            const float* ap = Sp + (long)r * NH + col0 + tx8;
            float4 a0 = __ldcg((const float4*)ap);
            float4 a1 = __ldcg((const float4*)(ap + 4));
            float4 v0 = make_float4(x0.x + a0.x, x0.y + a0.y, x1.x + a0.z, x1.y + a0.w);
            float4 v1 = make_float4(x2.x + a1.x, x2.y + a1.y, x3.x + a1.z, x3.y + a1.w);
            float* dp = D + (long)r * NH + col0 + tx8;
            *(float4*)dp = v0;
            *(float4*)(dp + 4) = v1;
        }

        __threadfence();
        __syncthreads();
        if (t == 0) {
            atomicAdd(&d_bar, 1u);
            unsigned target = 32u * (unsigned)(p + 1);
            while (atomicAdd(&d_bar, 0u) < target) {}
        }
        __syncthreads();
    }
}

// ---------------- output pass ----------------
__global__ void __launch_bounds__(128) out_kernel(const float* __restrict__ U,
                                                  float* __restrict__ out) {
    __shared__ ull As[32][132];
    __shared__ float Bs[32][68];
    int pj = blockIdx.x;
    int p = pj >> 5, j = pj & 31;
    int t = threadIdx.x;
    int KT = 32 + 2 * j;
    int tx8 = (t & 7) * 8, ty8 = (t >> 3) * 8;

    const float* xcRow = d_Xc + (long)p * CH + (long)t * NH;
    long uBase = (long)p * (LCH * BB * NU) + (long)t * NU;
    int kbB = t >> 3, c8B = (t & 7) * 8;

    ull acc[8][4];
    #pragma unroll
    for (int i = 0; i < 8; i++)
        #pragma unroll
        for (int jj = 0; jj < 4; jj++) acc[i][jj] = 0ull;

    float4 ra[4], rb0, rb1;
    #pragma unroll
    for (int h = 0; h < 4; h++) ra[h] = *(const float4*)(xcRow + h * 4);
    {
        const float* brow = d_Cbuf + (long)kbB * LDCB + j * NY + c8B;
        rb0 = *(const float4*)brow;
        rb1 = *(const float4*)(brow + 4);
    }
    stsAdup(As, t, ra);
    *(float4*)&Bs[kbB][c8B] = rb0;
    *(float4*)&Bs[kbB][c8B + 4] = rb1;
    __syncthreads();

    for (int kt = 0; kt < KT; kt++) {
        int cur = kt & 1;
        bool more = (kt + 1 < KT);
        if (more) {
            int k0 = (kt + 1) * 16;
            if (k0 < NH) {
                #pragma unroll
                for (int h = 0; h < 4; h++) ra[h] = *(const float4*)(xcRow + k0 + h * 4);
            } else {
                int kc = k0 - NH;
                #pragma unroll
                for (int h = 0; h < 4; h++) {
                    int k = kc + h * 4;
                    ra[h] = *(const float4*)(U + uBase + (long)(k >> 5) * (BB * NU) + (k & 31));
                }
            }
            int kb = k0 + kbB;
            const float* brow;
            if (kb < NH) {
                brow = d_Cbuf + (long)kb * LDCB + j * NY + c8B;
            } else {
                int kc = kb - NH;
                brow = d_Hd + (long)((j - 1 - (kc >> 5)) * NU + (kc & 31)) * NY + c8B;
            }
            rb0 = *(const float4*)brow;
            rb1 = *(const float4*)(brow + 4);
        }
        core16d(As + cur * 16, Bs + cur * 16, ty8, tx8, acc);
        if (more) {
            stsAdup(As + (cur ^ 1) * 16, t, ra);
            *(float4*)&Bs[(cur ^ 1) * 16 + kbB][c8B] = rb0;
            *(float4*)&Bs[(cur ^ 1) * 16 + kbB][c8B + 4] = rb1;
        }
        __syncthreads();
    }

    float4 yb0 = *(const float4*)(d_yb + j * NY + tx8);
    float4 yb1 = *(const float4*)(d_yb + j * NY + tx8 + 4);
    float* obase = out + (long)pj * (BB * NY);
    #pragma unroll
    for (int e = 0; e < 8; e++) {
        int r = ty8 + e;
        float2 x0 = up2(acc[e][0]), x1 = up2(acc[e][1]);
        float2 x2 = up2(acc[e][2]), x3 = up2(acc[e][3]);
        float4 v0 = make_float4(x0.x + yb0.x, x0.y + yb0.y, x1.x + yb0.z, x1.y + yb0.w);
        float4 v1 = make_float4(x2.x + yb1.x, x2.y + yb1.y, x3.x + yb1.z, x3.y + yb1.w);
        float* op = obase + (long)r * NY + tx8;
        *(float4*)op = v0;
        *(float4*)(op + 4) = v1;
    }
}

// ---------------- host ----------------
static int blocksFor(int lvl) {
    if (lvl <= 5) {
        int cb = 4 << (lvl - 1);
        int rt = (32 << (lvl - 1)) / 128;
        if (rt < 1) rt = 1;
        return 32 + cb + 8 * rt;
    }
    if (lvl == 6) return 40;
    return 32;
}

extern "C" void kernel_launch(void* const* d_in, const int* in_sizes, int n_in,
                              void* d_out, int out_size) {
    const float* y0     = (const float*)d_in[0];
    const float* U      = (const float*)d_in[1];
    const float* y2x_w  = (const float*)d_in[2];
    const float* y2x_b  = (const float*)d_in[3];
    const float* xu2x_w = (const float*)d_in[4];
    const float* xu2x_b = (const float*)d_in[5];
    const float* x2y_w  = (const float*)d_in[6];
    const float* x2y_b  = (const float*)d_in[7];
    float* out = (float*)d_out;

    float *pP, *pXc, *pS32, *pS64, *pS128, *pS256;
    cudaGetSymbolAddress((void**)&pP, d_Pow);
    cudaGetSymbolAddress((void**)&pXc, d_Xc);
    cudaGetSymbolAddress((void**)&pS32, d_S32);
    cudaGetSymbolAddress((void**)&pS64, d_S64);
    cudaGetSymbolAddress((void**)&pS128, d_S128);
    cudaGetSymbolAddress((void**)&pS256, d_S256);
    const long SZ = NH * NH;
    const float* pPow32  = pP + 4 * SZ;
    const float* pPow64  = pP + 5 * SZ;
    const float* pPow128 = pP + 6 * SZ;

    transA_kernel<<<dim3(16, 16), dim3(32, 8)>>>(xu2x_w);
    prep2_kernel<<<128, 256>>>(y0, y2x_w, y2x_b, xu2x_w, x2y_w);
    svec_kernel<<<1, NH>>>(xu2x_b, x2y_b);

    // fused precompute: 8 dependency levels
    for (int lvl = 1; lvl <= 8; lvl++)
        mgemm_kernel<<<blocksFor(lvl), 128>>>(lvl);

    // S32 per chunk
    s32_kernel<<<dim3(NH / 64, PCH), 128>>>(U);
    // combine tree
    gemm_f<<<dim3(8, PCH / 2), 128>>>(pS32, 2L * CH, NH, pPow32, NH,
                                      pS32 + CH, 2L * CH, pS64, CH, NH, NH);
    gemm_f<<<dim3(8, PCH / 4), 128>>>(pS64, 2L * CH, NH, pPow64, NH,
                                      pS64 + CH, 2L * CH, pS128, CH, NH, NH);
    gemm_f<<<dim3(8, PCH / 8), 128>>>(pS128, 2L * CH, NH, pPow128, NH,
                                      pS128 + CH, 2L * CH, pS256, CH, NH, NH);

    // 8 sequential steps of A^256 in one persistent kernel
    seq_persist<<<32, 128>>>();

    // fill tree: Xc[8r+4], then Xc[4m+2], then Xc[2m+1]
    gemm_f<<<dim3(8, PCH / 8), 128>>>(pXc, 8L * CH, NH, pPow128, NH,
                                      pS128, 2L * CH, pXc + 4L * CH, 8L * CH, NH, NH);
    gemm_f<<<dim3(8, PCH / 4), 128>>>(pXc, 4L * CH, NH, pPow64, NH,
                                      pS64, 2L * CH, pXc + 2L * CH, 4L * CH, NH, NH);
    gemm_f<<<dim3(8, PCH / 2), 128>>>(pXc, 2L * CH, NH, pPow32, NH,
                                      pS32, 2L * CH, pXc + CH, 2L * CH, NH, NH);

    // output pass: 2049 (p,j) tiles
    out_kernel<<<PCH * LCH + 1, 128>>>(U, out);

    (void)in_sizes; (void)n_in; (void)out_size;
}